// round 15
// baseline (speedup 1.0000x reference)
#include <cuda_runtime.h>
#include <cuda_fp16.h>
#include <cstdint>
#include <cstddef>

// Problem constants (match reference)
#define NROWS 50000
#define MROWS 20000
#define HIDC  256
#define OUTC  64
#define NNZ_HHT 1600000
#define NNZ_H   1000000
#define NNZ_HT  1000000
#define NNZ_HTH  640000

#define NB_N 49   // ceil(NROWS/1024)
#define NB_M 20   // ceil(MROWS/1024)
#define SCAN_BLOCKS (2 * NB_N + 2 * NB_M)   // 138 (all co-resident on 148 SMs)

// GEMM tiling: BM=128, BN=64 -> tiles per GEMM
#define GXT 1564   // 4 col-tiles * 391 row-tiles (x@W0, Nc=256)
#define GYT 628    // 4 * 157                     (y@W0)
#define HIST_BLOCKS 1024
#define SCAT_BLOCKS 1024
#define K2_BLOCKS (GXT + HIST_BLOCKS)             // 2588
#define K6_BLOCKS (2 * GYT + (SCAT_BLOCKS - GYT)) // 1652

// ---------------------------------------------------------------------------
// Static device scratch. Gather tables AND x1/y1 are fp16.
// ---------------------------------------------------------------------------
__device__ __align__(16) __half g_xw0[(size_t)NROWS * HIDC];
__device__ __align__(16) __half g_yw0[(size_t)MROWS * HIDC];
__device__ __align__(16) __half g_x1 [(size_t)NROWS * HIDC];
__device__ __align__(16) __half g_y1 [(size_t)MROWS * HIDC];
__device__ __align__(16) __half g_xw1[(size_t)NROWS * OUTC];
__device__ __align__(16) __half g_yw1[(size_t)MROWS * OUTC];

// CSR structures (built on device each launch).
// cnt arrays are zeroed at the END of scan_fused (static zero-init covers run 1).
__device__ int  g_cnt_hht[NROWS],  g_rp_hht[NROWS + 1],  g_cur_hht[NROWS];
__device__ int  g_cnt_h  [NROWS],  g_rp_h  [NROWS + 1],  g_cur_h  [NROWS];
__device__ int  g_cnt_ht [MROWS],  g_rp_ht [MROWS + 1],  g_cur_ht [MROWS];
__device__ int  g_cnt_hth[MROWS],  g_rp_hth[MROWS + 1],  g_cur_hth[MROWS];
__device__ int  g_aux_hht[64], g_aux_h[64], g_aux_ht[64], g_aux_hth[64];
__device__ unsigned g_bar;   // monotonic grid-barrier ticket counter
__device__ int2 g_pe_hht[NNZ_HHT];
__device__ int2 g_pe_h  [NNZ_H];
__device__ int2 g_pe_ht [NNZ_HT];
__device__ int2 g_pe_hth[NNZ_HTH];

__device__ __forceinline__ float leaky(float v) {
    return v >= 0.0f ? v : 0.2f * v;
}
__device__ __forceinline__ uint32_t smem_u32(const void* p) {
    return (uint32_t)__cvta_generic_to_shared(p);
}

// ===========================================================================
// Tensor-core GEMM body, register-prefetch pipelined:
// C[Mr,Nc](fp16) = A[Mr,K] @ B[K,Nc](fp32); A fp32 (layer 0) or fp16 (layer 1).
// BM=128, BN=64, BK=32; 8 warps (4m x 2n), warp tile 32x32 via m16n8k16 mma.
// Per iter: store staged regs -> smem, sync, prefetch next tile (LDG hidden
// under mma), mma, sync.
// ===========================================================================
template<typename AT>
__device__ __forceinline__
void gemm_mma_body(const AT* __restrict__ A, const float* __restrict__ B,
                   __half* __restrict__ C, int Mr, int K, int Nc, int bx, int by)
{
    constexpr int BM = 128, BN = 64, BK = 32;
    __shared__ __half As[BM][BK + 8];
    __shared__ __half Bs[BK][BN + 8];

    const int tid  = threadIdx.x;
    const int lane = tid & 31;
    const int wid  = tid >> 5;
    const int wm   = wid >> 1;
    const int wn   = wid & 1;
    const int row0 = by * BM;
    const int col0 = bx * BN;

    float acc[2][4][4];
    #pragma unroll
    for (int i = 0; i < 2; ++i)
        #pragma unroll
        for (int j = 0; j < 4; ++j)
            #pragma unroll
            for (int e = 0; e < 4; ++e) acc[i][j][e] = 0.f;

    // register staging for the pipelined tile
    float4 aF[4];
    uint4  aH[2];
    float4 bF[2];

    // ---- prologue: load k0 = 0 tile into registers ----
    if (sizeof(AT) == 4) {
        #pragma unroll
        for (int t = 0; t < 4; ++t) {
            const int li = tid + t * 256;
            const int r  = li >> 3;
            const int kc = (li & 7) * 4;
            aF[t] = make_float4(0.f, 0.f, 0.f, 0.f);
            if (row0 + r < Mr)
                aF[t] = *(const float4*)((const float*)A + (size_t)(row0 + r) * K + kc);
        }
    } else {
        #pragma unroll
        for (int t = 0; t < 2; ++t) {
            const int li = tid + t * 256;
            const int r  = li >> 2;
            const int kc = (li & 3) * 8;
            aH[t] = make_uint4(0, 0, 0, 0);
            if (row0 + r < Mr)
                aH[t] = *(const uint4*)((const __half*)A + (size_t)(row0 + r) * K + kc);
        }
    }
    #pragma unroll
    for (int t = 0; t < 2; ++t) {
        const int li = tid + t * 256;
        const int r  = li >> 4;
        const int c  = (li & 15) * 4;
        bF[t] = *(const float4*)(B + (size_t)r * Nc + col0 + c);
    }

    for (int k0 = 0; k0 < K; k0 += BK) {
        // ---- store staged registers into smem (with fp32->fp16 convert) ----
        if (sizeof(AT) == 4) {
            #pragma unroll
            for (int t = 0; t < 4; ++t) {
                const int li = tid + t * 256;
                const int r  = li >> 3;
                const int kc = (li & 7) * 4;
                *(__half2*)&As[r][kc]     = __floats2half2_rn(aF[t].x, aF[t].y);
                *(__half2*)&As[r][kc + 2] = __floats2half2_rn(aF[t].z, aF[t].w);
            }
        } else {
            #pragma unroll
            for (int t = 0; t < 2; ++t) {
                const int li = tid + t * 256;
                const int r  = li >> 2;
                const int kc = (li & 3) * 8;
                *(uint4*)&As[r][kc] = aH[t];
            }
        }
        #pragma unroll
        for (int t = 0; t < 2; ++t) {
            const int li = tid + t * 256;
            const int r  = li >> 4;
            const int c  = (li & 15) * 4;
            *(__half2*)&Bs[r][c]     = __floats2half2_rn(bF[t].x, bF[t].y);
            *(__half2*)&Bs[r][c + 2] = __floats2half2_rn(bF[t].z, bF[t].w);
        }
        __syncthreads();

        // ---- prefetch next k0 tile (LDG latency hidden under mma below) ----
        const int kn = k0 + BK;
        if (kn < K) {
            if (sizeof(AT) == 4) {
                #pragma unroll
                for (int t = 0; t < 4; ++t) {
                    const int li = tid + t * 256;
                    const int r  = li >> 3;
                    const int kc = (li & 7) * 4;
                    aF[t] = make_float4(0.f, 0.f, 0.f, 0.f);
                    if (row0 + r < Mr)
                        aF[t] = *(const float4*)((const float*)A + (size_t)(row0 + r) * K + kn + kc);
                }
            } else {
                #pragma unroll
                for (int t = 0; t < 2; ++t) {
                    const int li = tid + t * 256;
                    const int r  = li >> 2;
                    const int kc = (li & 3) * 8;
                    aH[t] = make_uint4(0, 0, 0, 0);
                    if (row0 + r < Mr)
                        aH[t] = *(const uint4*)((const __half*)A + (size_t)(row0 + r) * K + kn + kc);
                }
            }
            #pragma unroll
            for (int t = 0; t < 2; ++t) {
                const int li = tid + t * 256;
                const int r  = li >> 4;
                const int c  = (li & 15) * 4;
                bF[t] = *(const float4*)(B + (size_t)(kn + r) * Nc + col0 + c);
            }
        }

        // ---- mma over the smem tile ----
        #pragma unroll
        for (int kk = 0; kk < BK; kk += 16) {
            uint32_t a[2][4];
            #pragma unroll
            for (int mi = 0; mi < 2; ++mi) {
                const int rsel = wm * 32 + mi * 16 + (lane & 15);
                const int csel = kk + (lane >> 4) * 8;
                const uint32_t addr = smem_u32(&As[rsel][csel]);
                asm volatile("ldmatrix.sync.aligned.m8n8.x4.shared.b16 {%0,%1,%2,%3}, [%4];"
                    : "=r"(a[mi][0]), "=r"(a[mi][1]), "=r"(a[mi][2]), "=r"(a[mi][3])
                    : "r"(addr));
            }
            uint32_t bf[4][2];
            #pragma unroll
            for (int nb = 0; nb < 2; ++nb) {
                const int ksel = kk + (lane & 15);
                const int nsel = wn * 32 + nb * 16 + (lane >> 4) * 8;
                const uint32_t addr = smem_u32(&Bs[ksel][nsel]);
                uint32_t r0, r1, r2, r3;
                asm volatile("ldmatrix.sync.aligned.m8n8.x4.trans.shared.b16 {%0,%1,%2,%3}, [%4];"
                    : "=r"(r0), "=r"(r1), "=r"(r2), "=r"(r3) : "r"(addr));
                bf[nb * 2 + 0][0] = r0; bf[nb * 2 + 0][1] = r1;
                bf[nb * 2 + 1][0] = r2; bf[nb * 2 + 1][1] = r3;
            }
            #pragma unroll
            for (int mi = 0; mi < 2; ++mi)
                #pragma unroll
                for (int nj = 0; nj < 4; ++nj)
                    asm volatile("mma.sync.aligned.m16n8k16.row.col.f32.f16.f16.f32 "
                        "{%0,%1,%2,%3}, {%4,%5,%6,%7}, {%8,%9}, {%0,%1,%2,%3};"
                        : "+f"(acc[mi][nj][0]), "+f"(acc[mi][nj][1]),
                          "+f"(acc[mi][nj][2]), "+f"(acc[mi][nj][3])
                        : "r"(a[mi][0]), "r"(a[mi][1]), "r"(a[mi][2]), "r"(a[mi][3]),
                          "r"(bf[nj][0]), "r"(bf[nj][1]));
        }
        __syncthreads();
    }

    const int g  = lane >> 2;
    const int t4 = lane & 3;
    #pragma unroll
    for (int mi = 0; mi < 2; ++mi) {
        #pragma unroll
        for (int nj = 0; nj < 4; ++nj) {
            const int col = col0 + wn * 32 + nj * 8 + t4 * 2;
            const int ra = row0 + wm * 32 + mi * 16 + g;
            const int rb = ra + 8;
            if (ra < Mr)
                *(__half2*)(C + (size_t)ra * Nc + col) =
                    __floats2half2_rn(acc[mi][nj][0], acc[mi][nj][1]);
            if (rb < Mr)
                *(__half2*)(C + (size_t)rb * Nc + col) =
                    __floats2half2_rn(acc[mi][nj][2], acc[mi][nj][3]);
        }
    }
}

// ===========================================================================
// K1: x@W0 (mma) interleaved with the 4-matrix histogram.
// ===========================================================================
__global__ __launch_bounds__(256)
void fused_gemmx_hist_kernel(const float* __restrict__ x, const float* __restrict__ W0,
                             __half* __restrict__ xw0,
                             const int* __restrict__ r0, int n0,
                             const int* __restrict__ r1, int n1,
                             const int* __restrict__ r2, int n2,
                             const int* __restrict__ r3, int n3)
{
    const int b = blockIdx.x;
    int gid = -1, hb = -1;
    if (b < 2 * HIST_BLOCKS) { if ((b & 1) == 0) gid = b >> 1; else hb = b >> 1; }
    else                     gid = b - HIST_BLOCKS;

    if (gid >= 0) {
        gemm_mma_body<float>(x, W0, xw0, NROWS, HIDC, HIDC, gid & 3, gid >> 2);
    } else {
        const int total = n0 + n1 + n2 + n3;
        const int stride = HIST_BLOCKS * 256;
        for (int e = hb * 256 + threadIdx.x; e < total; e += stride) {
            if (e < n0)                atomicAdd(g_cnt_hht + __ldcs(r0 + e), 1);
            else if (e < n0 + n1)      atomicAdd(g_cnt_h   + __ldcs(r1 + e - n0), 1);
            else if (e < n0 + n1 + n2) atomicAdd(g_cnt_ht  + __ldcs(r2 + e - n0 - n1), 1);
            else                       atomicAdd(g_cnt_hth + __ldcs(r3 + e - n0 - n1 - n2), 1);
        }
    }
}

// ===========================================================================
// Fused rowptr build: per-block scan -> grid barrier -> aux prefix -> apply.
// Zeroes cnt after consumption (resets state for the next graph replay).
// ===========================================================================
__global__ __launch_bounds__(1024)
void scan_fused_kernel(int n0, int n1, int n2, int n3)
{
    const int b = blockIdx.x;
    int* cnt; int* rp; int* cur; int* aux; int n; int lb; int nnz;
    if (b < NB_N)              { cnt = g_cnt_hht; rp = g_rp_hht; cur = g_cur_hht; aux = g_aux_hht; n = NROWS; lb = b;                 nnz = n0; }
    else if (b < 2 * NB_N)     { cnt = g_cnt_h;   rp = g_rp_h;   cur = g_cur_h;   aux = g_aux_h;   n = NROWS; lb = b - NB_N;          nnz = n1; }
    else if (b < 2*NB_N+NB_M)  { cnt = g_cnt_ht;  rp = g_rp_ht;  cur = g_cur_ht;  aux = g_aux_ht;  n = MROWS; lb = b - 2*NB_N;        nnz = n2; }
    else                       { cnt = g_cnt_hth; rp = g_rp_hth; cur = g_cur_hth; aux = g_aux_hth; n = MROWS; lb = b - 2*NB_N - NB_M; nnz = n3; }

    __shared__ int s[1024];
    __shared__ int s_off;
    const int tid = threadIdx.x;
    const int i = lb * 1024 + tid;
    const int v = (i < n) ? cnt[i] : 0;
    s[tid] = v;
    __syncthreads();
    for (int off = 1; off < 1024; off <<= 1) {
        int t = (tid >= off) ? s[tid - off] : 0;
        __syncthreads();
        s[tid] += t;
        __syncthreads();
    }
    const int excl = s[tid] - v;
    if (tid == 1023) aux[lb] = s[1023];
    __syncthreads();

    if (tid == 0) {
        __threadfence();
        const unsigned ticket = atomicAdd(&g_bar, 1u);
        const unsigned target = ticket - (ticket % SCAN_BLOCKS) + SCAN_BLOCKS;
        while (*(volatile unsigned*)&g_bar < target) {}
        __threadfence();
        int off = 0;
        for (int k = 0; k < lb; ++k) off += aux[k];
        s_off = off;
    }
    __syncthreads();

    if (i < n) {
        const int r = excl + s_off;
        rp[i]  = r;
        cur[i] = r;
        cnt[i] = 0;
    }
    if (lb == 0 && tid == 0) rp[n] = nnz;
}

// ===========================================================================
// K3: y@W0 (mma) interleaved 1:1 with scatter.
// ===========================================================================
__global__ __launch_bounds__(256)
void fused_gemmy_scatter_kernel(const float* __restrict__ y, const float* __restrict__ W0,
                                __half* __restrict__ yw0,
                                const int* __restrict__ r0, const int* __restrict__ c0,
                                const float* __restrict__ v0, int n0,
                                const int* __restrict__ r1, const int* __restrict__ c1,
                                const float* __restrict__ v1, int n1,
                                const int* __restrict__ r2, const int* __restrict__ c2,
                                const float* __restrict__ v2, int n2,
                                const int* __restrict__ r3, const int* __restrict__ c3,
                                const float* __restrict__ v3, int n3)
{
    const int b = blockIdx.x;
    int sid;
    if (b < 2 * GYT) {
        if ((b & 1) == 0) {
            const int g = b >> 1;
            gemm_mma_body<float>(y, W0, yw0, MROWS, HIDC, HIDC, g & 3, g >> 2);
            return;
        }
        sid = b >> 1;
    } else {
        sid = GYT + (b - 2 * GYT);
    }

    const int total = n0 + n1 + n2 + n3;
    const int stride = SCAT_BLOCKS * 256;
    for (int e = sid * 256 + threadIdx.x; e < total; e += stride) {
        const int* rows; const int* cols; const float* vals;
        int* cur; int2* pe; int el;
        if (e < n0)                { rows = r0; cols = c0; vals = v0; cur = g_cur_hht; pe = g_pe_hht; el = e; }
        else if (e < n0 + n1)      { rows = r1; cols = c1; vals = v1; cur = g_cur_h;   pe = g_pe_h;   el = e - n0; }
        else if (e < n0 + n1 + n2) { rows = r2; cols = c2; vals = v2; cur = g_cur_ht;  pe = g_pe_ht;  el = e - n0 - n1; }
        else                       { rows = r3; cols = c3; vals = v3; cur = g_cur_hth; pe = g_pe_hth; el = e - n0 - n1 - n2; }
        const int r = __ldcs(rows + el);
        const int pos = atomicAdd(cur + r, 1);
        __stcs(pe + pos, make_int2(__ldcs(cols + el), __float_as_int(__ldcs(vals + el))));
    }
}

// ===========================================================================
// Merged CSR SpMM row bodies, fp16 gather sources, fp32 accumulation.
// ===========================================================================
__device__ __forceinline__
void spmm256_row_h(const int* __restrict__ rp, const int2* __restrict__ pe,
                   const __half* __restrict__ src, int row, int lane, float acc[8])
{
    const int s0 = __ldg(rp + row);
    const int s1 = __ldg(rp + row + 1);
    if (s0 >= s1) return;

    int2 e = (s0 + lane < s1) ? __ldcs(pe + s0 + lane) : make_int2(0, 0);
    for (int j0 = s0; j0 < s1; j0 += 32) {
        const int2 ecur = e;
        const int jn = j0 + 32;
        if (jn < s1)
            e = (jn + lane < s1) ? __ldcs(pe + jn + lane) : make_int2(0, 0);
        const int cnt = min(32, s1 - j0);
        for (int t = 0; t < cnt; ++t) {
            const int   ct = __shfl_sync(0xffffffffu, ecur.x, t);
            const float vt = __int_as_float(__shfl_sync(0xffffffffu, ecur.y, t));
            const uint4 u = __ldg((const uint4*)(src + (size_t)ct * HIDC) + lane);
            const __half2* h2 = (const __half2*)&u;
            float2 f;
            f = __half22float2(h2[0]); acc[0] += vt * f.x; acc[1] += vt * f.y;
            f = __half22float2(h2[1]); acc[2] += vt * f.x; acc[3] += vt * f.y;
            f = __half22float2(h2[2]); acc[4] += vt * f.x; acc[5] += vt * f.y;
            f = __half22float2(h2[3]); acc[6] += vt * f.x; acc[7] += vt * f.y;
        }
    }
}

// K=256 merged SpMM over BOTH row spaces; writes leaky(sumA)+leaky(sumB) fp16.
__global__ __launch_bounds__(256)
void spmm256_dual_kernel(const __half* __restrict__ xw0, const __half* __restrict__ yw0,
                         __half* __restrict__ x1, __half* __restrict__ y1)
{
    const int lane = threadIdx.x & 31;
    const int wb   = blockIdx.x * 8 + (threadIdx.x >> 5);

    float a[8] = {}, b[8] = {};
    __half* dst;
    int row;
    if (wb < NROWS) {
        row = wb;
        spmm256_row_h(g_rp_hht, g_pe_hht, xw0, row, lane, a);
        spmm256_row_h(g_rp_h,   g_pe_h,   yw0, row, lane, b);
        dst = x1;
    } else {
        row = wb - NROWS;
        spmm256_row_h(g_rp_ht,  g_pe_ht,  xw0, row, lane, a);
        spmm256_row_h(g_rp_hth, g_pe_hth, yw0, row, lane, b);
        dst = y1;
    }

    __half2 o[4];
    #pragma unroll
    for (int i = 0; i < 4; ++i)
        o[i] = __floats2half2_rn(leaky(a[2*i]) + leaky(b[2*i]),
                                 leaky(a[2*i+1]) + leaky(b[2*i+1]));
    __stcs((uint4*)(dst + (size_t)row * HIDC + lane * 8), *(uint4*)o);
}

__device__ __forceinline__
void spmm64_row_h(const int* __restrict__ rp, const int2* __restrict__ pe,
                  const __half* __restrict__ src, int row, int lane16, unsigned gmask,
                  float acc[4])
{
    const int s0 = __ldg(rp + row);
    const int s1 = __ldg(rp + row + 1);
    for (int j0 = s0; j0 < s1; j0 += 16) {
        int2 e = make_int2(0, 0);
        if (j0 + lane16 < s1) e = __ldcs(pe + j0 + lane16);
        const int cnt = min(16, s1 - j0);
        for (int t = 0; t < cnt; ++t) {
            const int   ct = __shfl_sync(gmask, e.x, t, 16);
            const float vt = __int_as_float(__shfl_sync(gmask, e.y, t, 16));
            const uint2 u = __ldg((const uint2*)(src + (size_t)ct * OUTC) + lane16);
            const __half2* h2 = (const __half2*)&u;
            float2 f;
            f = __half22float2(h2[0]); acc[0] += vt * f.x; acc[1] += vt * f.y;
            f = __half22float2(h2[1]); acc[2] += vt * f.x; acc[3] += vt * f.y;
        }
    }
}

// K=64 merged SpMM over both row spaces; writes final fp32 output.
__global__ __launch_bounds__(256)
void spmm64_dual_kernel(const __half* __restrict__ xw1, const __half* __restrict__ yw1,
                        float* __restrict__ out)
{
    const int lane32 = threadIdx.x & 31;
    const int lane16 = threadIdx.x & 15;
    const unsigned gmask = 0xFFFFu << (lane32 & 16);
    const int wb = blockIdx.x * 16 + (threadIdx.x >> 4);

    float a[4] = {}, b[4] = {};
    float* dst;
    int row;
    if (wb < NROWS) {
        row = wb;
        spmm64_row_h(g_rp_hht, g_pe_hht, xw1, row, lane16, gmask, a);
        spmm64_row_h(g_rp_h,   g_pe_h,   yw1, row, lane16, gmask, b);
        dst = out;
    } else {
        row = wb - NROWS;
        spmm64_row_h(g_rp_ht,  g_pe_ht,  xw1, row, lane16, gmask, a);
        spmm64_row_h(g_rp_hth, g_pe_hth, yw1, row, lane16, gmask, b);
        dst = out + (size_t)NROWS * OUTC;
    }

    float o[4];
    #pragma unroll
    for (int i = 0; i < 4; ++i) o[i] = leaky(a[i]) + leaky(b[i]);
    __stcs((float4*)(dst + (size_t)row * OUTC + lane16 * 4), *(float4*)&o[0]);
}

// K5: merged layer-1 GEMM (fp16 A, fp32 W1, fp16 out): [0,391) x1, rest y1.
#define G1X_BLOCKS 391
__global__ __launch_bounds__(256)
void gemm1_dual_kernel(const __half* __restrict__ x1, const __half* __restrict__ y1,
                       const float* __restrict__ W1,
                       __half* __restrict__ xw1, __half* __restrict__ yw1)
{
    const int b = blockIdx.x;
    if (b < G1X_BLOCKS)
        gemm_mma_body<__half>(x1, W1, xw1, NROWS, HIDC, OUTC, 0, b);
    else
        gemm_mma_body<__half>(y1, W1, yw1, MROWS, HIDC, OUTC, 0, b - G1X_BLOCKS);
}

// ---------------------------------------------------------------------------
// Launch
// ---------------------------------------------------------------------------
extern "C" void kernel_launch(void* const* d_in, const int* in_sizes, int n_in,
                              void* d_out, int out_size)
{
    const float* x   = (const float*)d_in[0];
    const float* y   = (const float*)d_in[1];
    const float* W0  = (const float*)d_in[2];
    const float* W1  = (const float*)d_in[3];
    const int*   hht_r = (const int*)d_in[4];
    const int*   hht_c = (const int*)d_in[5];
    const float* hht_v = (const float*)d_in[6];
    const int*   h_r   = (const int*)d_in[7];
    const int*   h_c   = (const int*)d_in[8];
    const float* h_v   = (const float*)d_in[9];
    const int*   ht_r  = (const int*)d_in[10];
    const int*   ht_c  = (const int*)d_in[11];
    const float* ht_v  = (const float*)d_in[12];
    const int*   hth_r = (const int*)d_in[13];
    const int*   hth_c = (const int*)d_in[14];
    const float* hth_v = (const float*)d_in[15];

    const int nnz_hht = in_sizes[4];
    const int nnz_h   = in_sizes[7];
    const int nnz_ht  = in_sizes[10];
    const int nnz_hth = in_sizes[13];

    __half *xw0, *yw0, *x1, *y1, *xw1, *yw1;
    cudaGetSymbolAddress((void**)&xw0, g_xw0);
    cudaGetSymbolAddress((void**)&yw0, g_yw0);
    cudaGetSymbolAddress((void**)&x1,  g_x1);
    cudaGetSymbolAddress((void**)&y1,  g_y1);
    cudaGetSymbolAddress((void**)&xw1, g_xw1);
    cudaGetSymbolAddress((void**)&yw1, g_yw1);

    float* out = (float*)d_out;

    // K1: x@W0 tensor-core GEMM interleaved with the 4-matrix histogram
    fused_gemmx_hist_kernel<<<K2_BLOCKS, 256>>>(
        x, W0, xw0,
        hht_r, nnz_hht, h_r, nnz_h, ht_r, nnz_ht, hth_r, nnz_hth);

    // K2: fused rowptr build (scan + grid barrier + apply + cnt reset)
    scan_fused_kernel<<<SCAN_BLOCKS, 1024>>>(nnz_hht, nnz_h, nnz_ht, nnz_hth);

    // K3: y@W0 tensor-core GEMM interleaved with the COO->CSR scatter
    fused_gemmy_scatter_kernel<<<K6_BLOCKS, 256>>>(
        y, W0, yw0,
        hht_r, hht_c, hht_v, nnz_hht,
        h_r,   h_c,   h_v,   nnz_h,
        ht_r,  ht_c,  ht_v,  nnz_ht,
        hth_r, hth_c, hth_v, nnz_hth);

    // K4: layer-0 SpMM over both row spaces (fp16 gathers/out, fp32 accum)
    spmm256_dual_kernel<<<NROWS / 8 + MROWS / 8, 256>>>(xw0, yw0, x1, y1);

    // K5: layer-1 tensor-core GEMM (fp16 in, fp16 out)
    gemm1_dual_kernel<<<G1X_BLOCKS + 157, 256>>>(x1, y1, W1, xw1, yw1);

    // K6: layer-1 SpMM (fp16 gathers), writes final fp32 output
    spmm64_dual_kernel<<<NROWS / 16 + MROWS / 16, 256>>>(xw1, yw1, out);
}

// round 17
// speedup vs baseline: 1.0390x; 1.0390x over previous
#include <cuda_runtime.h>
#include <cuda_fp16.h>
#include <cstdint>
#include <cstddef>

// Problem constants (match reference)
#define NROWS 50000
#define MROWS 20000
#define HIDC  256
#define OUTC  64
#define NNZ_HHT 1600000
#define NNZ_H   1000000
#define NNZ_HT  1000000
#define NNZ_HTH  640000

#define NB_N 49   // ceil(NROWS/1024)
#define NB_M 20   // ceil(MROWS/1024)
#define SCAN_BLOCKS (2 * NB_N + 2 * NB_M)   // 138 (all co-resident on 148 SMs)

// GEMM tiling: BM=128, BN=64 -> tiles per GEMM
#define GXT 1564   // 4 col-tiles * 391 row-tiles (x@W0, Nc=256)
#define GYT 628    // 4 * 157                     (y@W0)
#define HIST_BLOCKS 1024
#define SCAT_BLOCKS 1024
#define K2_BLOCKS (GXT + HIST_BLOCKS)             // 2588
#define K6_BLOCKS (2 * GYT + (SCAT_BLOCKS - GYT)) // 1652

// ---------------------------------------------------------------------------
// Static device scratch. Gather tables AND x1/y1 are fp16.
// ---------------------------------------------------------------------------
__device__ __align__(16) __half g_xw0[(size_t)NROWS * HIDC];
__device__ __align__(16) __half g_yw0[(size_t)MROWS * HIDC];
__device__ __align__(16) __half g_x1 [(size_t)NROWS * HIDC];
__device__ __align__(16) __half g_y1 [(size_t)MROWS * HIDC];
__device__ __align__(16) __half g_xw1[(size_t)NROWS * OUTC];
__device__ __align__(16) __half g_yw1[(size_t)MROWS * OUTC];

// CSR structures (built on device each launch).
// cnt arrays are zeroed at the END of scan_fused (static zero-init covers run 1).
__device__ int  g_cnt_hht[NROWS],  g_rp_hht[NROWS + 1],  g_cur_hht[NROWS];
__device__ int  g_cnt_h  [NROWS],  g_rp_h  [NROWS + 1],  g_cur_h  [NROWS];
__device__ int  g_cnt_ht [MROWS],  g_rp_ht [MROWS + 1],  g_cur_ht [MROWS];
__device__ int  g_cnt_hth[MROWS],  g_rp_hth[MROWS + 1],  g_cur_hth[MROWS];
__device__ int  g_aux_hht[64], g_aux_h[64], g_aux_ht[64], g_aux_hth[64];
__device__ unsigned g_bar;   // monotonic grid-barrier ticket counter
__device__ int2 g_pe_hht[NNZ_HHT];
__device__ int2 g_pe_h  [NNZ_H];
__device__ int2 g_pe_ht [NNZ_HT];
__device__ int2 g_pe_hth[NNZ_HTH];

__device__ __forceinline__ float leaky(float v) {
    return v >= 0.0f ? v : 0.2f * v;
}
__device__ __forceinline__ uint32_t smem_u32(const void* p) {
    return (uint32_t)__cvta_generic_to_shared(p);
}

// ===========================================================================
// Tensor-core GEMM body (R14 synchronous version — the measured-best):
// C[Mr,Nc](fp16) = A[Mr,K] @ B[K,Nc](fp32); A fp32 (layer 0) or fp16 (layer 1).
// BM=128, BN=64, BK=32; 8 warps (4m x 2n), warp tile 32x32 via m16n8k16 mma.
// ===========================================================================
template<typename AT>
__device__ __forceinline__
void gemm_mma_body(const AT* __restrict__ A, const float* __restrict__ B,
                   __half* __restrict__ C, int Mr, int K, int Nc, int bx, int by)
{
    constexpr int BM = 128, BN = 64, BK = 32;
    __shared__ __half As[BM][BK + 8];
    __shared__ __half Bs[BK][BN + 8];

    const int tid  = threadIdx.x;
    const int lane = tid & 31;
    const int wid  = tid >> 5;
    const int wm   = wid >> 1;
    const int wn   = wid & 1;
    const int row0 = by * BM;
    const int col0 = bx * BN;

    float acc[2][4][4];
    #pragma unroll
    for (int i = 0; i < 2; ++i)
        #pragma unroll
        for (int j = 0; j < 4; ++j)
            #pragma unroll
            for (int e = 0; e < 4; ++e) acc[i][j][e] = 0.f;

    for (int k0 = 0; k0 < K; k0 += BK) {
        if (sizeof(AT) == 4) {
            #pragma unroll
            for (int t = 0; t < 4; ++t) {
                const int li = tid + t * 256;
                const int r  = li >> 3;
                const int kc = (li & 7) * 4;
                float4 v = make_float4(0.f, 0.f, 0.f, 0.f);
                if (row0 + r < Mr)
                    v = *(const float4*)((const float*)A + (size_t)(row0 + r) * K + k0 + kc);
                *(__half2*)&As[r][kc]     = __floats2half2_rn(v.x, v.y);
                *(__half2*)&As[r][kc + 2] = __floats2half2_rn(v.z, v.w);
            }
        } else {
            #pragma unroll
            for (int t = 0; t < 2; ++t) {
                const int li = tid + t * 256;
                const int r  = li >> 2;
                const int kc = (li & 3) * 8;
                uint4 v = make_uint4(0, 0, 0, 0);
                if (row0 + r < Mr)
                    v = *(const uint4*)((const __half*)A + (size_t)(row0 + r) * K + k0 + kc);
                *(uint4*)&As[r][kc] = v;
            }
        }
        #pragma unroll
        for (int t = 0; t < 2; ++t) {
            const int li = tid + t * 256;
            const int r  = li >> 4;
            const int c  = (li & 15) * 4;
            const float4 v = *(const float4*)(B + (size_t)(k0 + r) * Nc + col0 + c);
            *(__half2*)&Bs[r][c]     = __floats2half2_rn(v.x, v.y);
            *(__half2*)&Bs[r][c + 2] = __floats2half2_rn(v.z, v.w);
        }
        __syncthreads();

        #pragma unroll
        for (int kk = 0; kk < BK; kk += 16) {
            uint32_t a[2][4];
            #pragma unroll
            for (int mi = 0; mi < 2; ++mi) {
                const int rsel = wm * 32 + mi * 16 + (lane & 15);
                const int csel = kk + (lane >> 4) * 8;
                const uint32_t addr = smem_u32(&As[rsel][csel]);
                asm volatile("ldmatrix.sync.aligned.m8n8.x4.shared.b16 {%0,%1,%2,%3}, [%4];"
                    : "=r"(a[mi][0]), "=r"(a[mi][1]), "=r"(a[mi][2]), "=r"(a[mi][3])
                    : "r"(addr));
            }
            uint32_t bf[4][2];
            #pragma unroll
            for (int nb = 0; nb < 2; ++nb) {
                const int ksel = kk + (lane & 15);
                const int nsel = wn * 32 + nb * 16 + (lane >> 4) * 8;
                const uint32_t addr = smem_u32(&Bs[ksel][nsel]);
                uint32_t r0, r1, r2, r3;
                asm volatile("ldmatrix.sync.aligned.m8n8.x4.trans.shared.b16 {%0,%1,%2,%3}, [%4];"
                    : "=r"(r0), "=r"(r1), "=r"(r2), "=r"(r3) : "r"(addr));
                bf[nb * 2 + 0][0] = r0; bf[nb * 2 + 0][1] = r1;
                bf[nb * 2 + 1][0] = r2; bf[nb * 2 + 1][1] = r3;
            }
            #pragma unroll
            for (int mi = 0; mi < 2; ++mi)
                #pragma unroll
                for (int nj = 0; nj < 4; ++nj)
                    asm volatile("mma.sync.aligned.m16n8k16.row.col.f32.f16.f16.f32 "
                        "{%0,%1,%2,%3}, {%4,%5,%6,%7}, {%8,%9}, {%0,%1,%2,%3};"
                        : "+f"(acc[mi][nj][0]), "+f"(acc[mi][nj][1]),
                          "+f"(acc[mi][nj][2]), "+f"(acc[mi][nj][3])
                        : "r"(a[mi][0]), "r"(a[mi][1]), "r"(a[mi][2]), "r"(a[mi][3]),
                          "r"(bf[nj][0]), "r"(bf[nj][1]));
        }
        __syncthreads();
    }

    const int g  = lane >> 2;
    const int t4 = lane & 3;
    #pragma unroll
    for (int mi = 0; mi < 2; ++mi) {
        #pragma unroll
        for (int nj = 0; nj < 4; ++nj) {
            const int col = col0 + wn * 32 + nj * 8 + t4 * 2;
            const int ra = row0 + wm * 32 + mi * 16 + g;
            const int rb = ra + 8;
            if (ra < Mr)
                *(__half2*)(C + (size_t)ra * Nc + col) =
                    __floats2half2_rn(acc[mi][nj][0], acc[mi][nj][1]);
            if (rb < Mr)
                *(__half2*)(C + (size_t)rb * Nc + col) =
                    __floats2half2_rn(acc[mi][nj][2], acc[mi][nj][3]);
        }
    }
}

// ===========================================================================
// K1: x@W0 (mma) interleaved with the 4-matrix histogram.
// ===========================================================================
__global__ __launch_bounds__(256)
void fused_gemmx_hist_kernel(const float* __restrict__ x, const float* __restrict__ W0,
                             __half* __restrict__ xw0,
                             const int* __restrict__ r0, int n0,
                             const int* __restrict__ r1, int n1,
                             const int* __restrict__ r2, int n2,
                             const int* __restrict__ r3, int n3)
{
    const int b = blockIdx.x;
    int gid = -1, hb = -1;
    if (b < 2 * HIST_BLOCKS) { if ((b & 1) == 0) gid = b >> 1; else hb = b >> 1; }
    else                     gid = b - HIST_BLOCKS;

    if (gid >= 0) {
        gemm_mma_body<float>(x, W0, xw0, NROWS, HIDC, HIDC, gid & 3, gid >> 2);
    } else {
        const int total = n0 + n1 + n2 + n3;
        const int stride = HIST_BLOCKS * 256;
        for (int e = hb * 256 + threadIdx.x; e < total; e += stride) {
            if (e < n0)                atomicAdd(g_cnt_hht + __ldcs(r0 + e), 1);
            else if (e < n0 + n1)      atomicAdd(g_cnt_h   + __ldcs(r1 + e - n0), 1);
            else if (e < n0 + n1 + n2) atomicAdd(g_cnt_ht  + __ldcs(r2 + e - n0 - n1), 1);
            else                       atomicAdd(g_cnt_hth + __ldcs(r3 + e - n0 - n1 - n2), 1);
        }
    }
}

// ===========================================================================
// Fused rowptr build: per-block scan -> grid barrier -> aux prefix -> apply.
// Zeroes cnt after consumption (resets state for the next graph replay).
// ===========================================================================
__global__ __launch_bounds__(1024)
void scan_fused_kernel(int n0, int n1, int n2, int n3)
{
    const int b = blockIdx.x;
    int* cnt; int* rp; int* cur; int* aux; int n; int lb; int nnz;
    if (b < NB_N)              { cnt = g_cnt_hht; rp = g_rp_hht; cur = g_cur_hht; aux = g_aux_hht; n = NROWS; lb = b;                 nnz = n0; }
    else if (b < 2 * NB_N)     { cnt = g_cnt_h;   rp = g_rp_h;   cur = g_cur_h;   aux = g_aux_h;   n = NROWS; lb = b - NB_N;          nnz = n1; }
    else if (b < 2*NB_N+NB_M)  { cnt = g_cnt_ht;  rp = g_rp_ht;  cur = g_cur_ht;  aux = g_aux_ht;  n = MROWS; lb = b - 2*NB_N;        nnz = n2; }
    else                       { cnt = g_cnt_hth; rp = g_rp_hth; cur = g_cur_hth; aux = g_aux_hth; n = MROWS; lb = b - 2*NB_N - NB_M; nnz = n3; }

    __shared__ int s[1024];
    __shared__ int s_off;
    const int tid = threadIdx.x;
    const int i = lb * 1024 + tid;
    const int v = (i < n) ? cnt[i] : 0;
    s[tid] = v;
    __syncthreads();
    for (int off = 1; off < 1024; off <<= 1) {
        int t = (tid >= off) ? s[tid - off] : 0;
        __syncthreads();
        s[tid] += t;
        __syncthreads();
    }
    const int excl = s[tid] - v;
    if (tid == 1023) aux[lb] = s[1023];
    __syncthreads();

    if (tid == 0) {
        __threadfence();
        const unsigned ticket = atomicAdd(&g_bar, 1u);
        const unsigned target = ticket - (ticket % SCAN_BLOCKS) + SCAN_BLOCKS;
        while (*(volatile unsigned*)&g_bar < target) {}
        __threadfence();
        int off = 0;
        for (int k = 0; k < lb; ++k) off += aux[k];
        s_off = off;
    }
    __syncthreads();

    if (i < n) {
        const int r = excl + s_off;
        rp[i]  = r;
        cur[i] = r;
        cnt[i] = 0;
    }
    if (lb == 0 && tid == 0) rp[n] = nnz;
}

// ===========================================================================
// K3: y@W0 (mma) interleaved 1:1 with scatter.
// ===========================================================================
__global__ __launch_bounds__(256)
void fused_gemmy_scatter_kernel(const float* __restrict__ y, const float* __restrict__ W0,
                                __half* __restrict__ yw0,
                                const int* __restrict__ r0, const int* __restrict__ c0,
                                const float* __restrict__ v0, int n0,
                                const int* __restrict__ r1, const int* __restrict__ c1,
                                const float* __restrict__ v1, int n1,
                                const int* __restrict__ r2, const int* __restrict__ c2,
                                const float* __restrict__ v2, int n2,
                                const int* __restrict__ r3, const int* __restrict__ c3,
                                const float* __restrict__ v3, int n3)
{
    const int b = blockIdx.x;
    int sid;
    if (b < 2 * GYT) {
        if ((b & 1) == 0) {
            const int g = b >> 1;
            gemm_mma_body<float>(y, W0, yw0, MROWS, HIDC, HIDC, g & 3, g >> 2);
            return;
        }
        sid = b >> 1;
    } else {
        sid = GYT + (b - 2 * GYT);
    }

    const int total = n0 + n1 + n2 + n3;
    const int stride = SCAT_BLOCKS * 256;
    for (int e = sid * 256 + threadIdx.x; e < total; e += stride) {
        const int* rows; const int* cols; const float* vals;
        int* cur; int2* pe; int el;
        if (e < n0)                { rows = r0; cols = c0; vals = v0; cur = g_cur_hht; pe = g_pe_hht; el = e; }
        else if (e < n0 + n1)      { rows = r1; cols = c1; vals = v1; cur = g_cur_h;   pe = g_pe_h;   el = e - n0; }
        else if (e < n0 + n1 + n2) { rows = r2; cols = c2; vals = v2; cur = g_cur_ht;  pe = g_pe_ht;  el = e - n0 - n1; }
        else                       { rows = r3; cols = c3; vals = v3; cur = g_cur_hth; pe = g_pe_hth; el = e - n0 - n1 - n2; }
        const int r = __ldcs(rows + el);
        const int pos = atomicAdd(cur + r, 1);
        __stcs(pe + pos, make_int2(__ldcs(cols + el), __float_as_int(__ldcs(vals + el))));
    }
}

// ===========================================================================
// Merged CSR SpMM row bodies, fp16 gather sources, fp32 accumulation.
// K=256 body: 2-way unrolled gather (both independent LDGs issued before
// either is consumed -> 2x per-lane MLP, ~4 extra registers).
// ===========================================================================
__device__ __forceinline__
void spmm256_consume(const uint4& u, float vt, float acc[8])
{
    const __half2* h2 = (const __half2*)&u;
    float2 f;
    f = __half22float2(h2[0]); acc[0] += vt * f.x; acc[1] += vt * f.y;
    f = __half22float2(h2[1]); acc[2] += vt * f.x; acc[3] += vt * f.y;
    f = __half22float2(h2[2]); acc[4] += vt * f.x; acc[5] += vt * f.y;
    f = __half22float2(h2[3]); acc[6] += vt * f.x; acc[7] += vt * f.y;
}

__device__ __forceinline__
void spmm256_row_h(const int* __restrict__ rp, const int2* __restrict__ pe,
                   const __half* __restrict__ src, int row, int lane, float acc[8])
{
    const int s0 = __ldg(rp + row);
    const int s1 = __ldg(rp + row + 1);
    for (int j0 = s0; j0 < s1; j0 += 32) {
        int2 e = make_int2(0, 0);
        if (j0 + lane < s1) e = __ldcs(pe + j0 + lane);
        const int cnt = min(32, s1 - j0);
        int t = 0;
        for (; t + 1 < cnt; t += 2) {
            const int   ct0 = __shfl_sync(0xffffffffu, e.x, t);
            const float vt0 = __int_as_float(__shfl_sync(0xffffffffu, e.y, t));
            const int   ct1 = __shfl_sync(0xffffffffu, e.x, t + 1);
            const float vt1 = __int_as_float(__shfl_sync(0xffffffffu, e.y, t + 1));
            const uint4 u0 = __ldg((const uint4*)(src + (size_t)ct0 * HIDC) + lane);
            const uint4 u1 = __ldg((const uint4*)(src + (size_t)ct1 * HIDC) + lane);
            spmm256_consume(u0, vt0, acc);
            spmm256_consume(u1, vt1, acc);
        }
        if (t < cnt) {
            const int   ct = __shfl_sync(0xffffffffu, e.x, t);
            const float vt = __int_as_float(__shfl_sync(0xffffffffu, e.y, t));
            const uint4 u = __ldg((const uint4*)(src + (size_t)ct * HIDC) + lane);
            spmm256_consume(u, vt, acc);
        }
    }
}

// K=256 merged SpMM over BOTH row spaces; writes leaky(sumA)+leaky(sumB) fp16.
__global__ __launch_bounds__(256)
void spmm256_dual_kernel(const __half* __restrict__ xw0, const __half* __restrict__ yw0,
                         __half* __restrict__ x1, __half* __restrict__ y1)
{
    const int lane = threadIdx.x & 31;
    const int wb   = blockIdx.x * 8 + (threadIdx.x >> 5);

    float a[8] = {}, b[8] = {};
    __half* dst;
    int row;
    if (wb < NROWS) {
        row = wb;
        spmm256_row_h(g_rp_hht, g_pe_hht, xw0, row, lane, a);
        spmm256_row_h(g_rp_h,   g_pe_h,   yw0, row, lane, b);
        dst = x1;
    } else {
        row = wb - NROWS;
        spmm256_row_h(g_rp_ht,  g_pe_ht,  xw0, row, lane, a);
        spmm256_row_h(g_rp_hth, g_pe_hth, yw0, row, lane, b);
        dst = y1;
    }

    __half2 o[4];
    #pragma unroll
    for (int i = 0; i < 4; ++i)
        o[i] = __floats2half2_rn(leaky(a[2*i]) + leaky(b[2*i]),
                                 leaky(a[2*i+1]) + leaky(b[2*i+1]));
    __stcs((uint4*)(dst + (size_t)row * HIDC + lane * 8), *(uint4*)o);
}

__device__ __forceinline__
void spmm64_row_h(const int* __restrict__ rp, const int2* __restrict__ pe,
                  const __half* __restrict__ src, int row, int lane16, unsigned gmask,
                  float acc[4])
{
    const int s0 = __ldg(rp + row);
    const int s1 = __ldg(rp + row + 1);
    for (int j0 = s0; j0 < s1; j0 += 16) {
        int2 e = make_int2(0, 0);
        if (j0 + lane16 < s1) e = __ldcs(pe + j0 + lane16);
        const int cnt = min(16, s1 - j0);
        for (int t = 0; t < cnt; ++t) {
            const int   ct = __shfl_sync(gmask, e.x, t, 16);
            const float vt = __int_as_float(__shfl_sync(gmask, e.y, t, 16));
            const uint2 u = __ldg((const uint2*)(src + (size_t)ct * OUTC) + lane16);
            const __half2* h2 = (const __half2*)&u;
            float2 f;
            f = __half22float2(h2[0]); acc[0] += vt * f.x; acc[1] += vt * f.y;
            f = __half22float2(h2[1]); acc[2] += vt * f.x; acc[3] += vt * f.y;
        }
    }
}

// K=64 merged SpMM over both row spaces; writes final fp32 output.
__global__ __launch_bounds__(256)
void spmm64_dual_kernel(const __half* __restrict__ xw1, const __half* __restrict__ yw1,
                        float* __restrict__ out)
{
    const int lane32 = threadIdx.x & 31;
    const int lane16 = threadIdx.x & 15;
    const unsigned gmask = 0xFFFFu << (lane32 & 16);
    const int wb = blockIdx.x * 16 + (threadIdx.x >> 4);

    float a[4] = {}, b[4] = {};
    float* dst;
    int row;
    if (wb < NROWS) {
        row = wb;
        spmm64_row_h(g_rp_hht, g_pe_hht, xw1, row, lane16, gmask, a);
        spmm64_row_h(g_rp_h,   g_pe_h,   yw1, row, lane16, gmask, b);
        dst = out;
    } else {
        row = wb - NROWS;
        spmm64_row_h(g_rp_ht,  g_pe_ht,  xw1, row, lane16, gmask, a);
        spmm64_row_h(g_rp_hth, g_pe_hth, yw1, row, lane16, gmask, b);
        dst = out + (size_t)NROWS * OUTC;
    }

    float o[4];
    #pragma unroll
    for (int i = 0; i < 4; ++i) o[i] = leaky(a[i]) + leaky(b[i]);
    __stcs((float4*)(dst + (size_t)row * OUTC + lane16 * 4), *(float4*)&o[0]);
}

// K5: merged layer-1 GEMM (fp16 A, fp32 W1, fp16 out): [0,391) x1, rest y1.
#define G1X_BLOCKS 391
__global__ __launch_bounds__(256)
void gemm1_dual_kernel(const __half* __restrict__ x1, const __half* __restrict__ y1,
                       const float* __restrict__ W1,
                       __half* __restrict__ xw1, __half* __restrict__ yw1)
{
    const int b = blockIdx.x;
    if (b < G1X_BLOCKS)
        gemm_mma_body<__half>(x1, W1, xw1, NROWS, HIDC, OUTC, 0, b);
    else
        gemm_mma_body<__half>(y1, W1, yw1, MROWS, HIDC, OUTC, 0, b - G1X_BLOCKS);
}

// ---------------------------------------------------------------------------
// Launch
// ---------------------------------------------------------------------------
extern "C" void kernel_launch(void* const* d_in, const int* in_sizes, int n_in,
                              void* d_out, int out_size)
{
    const float* x   = (const float*)d_in[0];
    const float* y   = (const float*)d_in[1];
    const float* W0  = (const float*)d_in[2];
    const float* W1  = (const float*)d_in[3];
    const int*   hht_r = (const int*)d_in[4];
    const int*   hht_c = (const int*)d_in[5];
    const float* hht_v = (const float*)d_in[6];
    const int*   h_r   = (const int*)d_in[7];
    const int*   h_c   = (const int*)d_in[8];
    const float* h_v   = (const float*)d_in[9];
    const int*   ht_r  = (const int*)d_in[10];
    const int*   ht_c  = (const int*)d_in[11];
    const float* ht_v  = (const float*)d_in[12];
    const int*   hth_r = (const int*)d_in[13];
    const int*   hth_c = (const int*)d_in[14];
    const float* hth_v = (const float*)d_in[15];

    const int nnz_hht = in_sizes[4];
    const int nnz_h   = in_sizes[7];
    const int nnz_ht  = in_sizes[10];
    const int nnz_hth = in_sizes[13];

    __half *xw0, *yw0, *x1, *y1, *xw1, *yw1;
    cudaGetSymbolAddress((void**)&xw0, g_xw0);
    cudaGetSymbolAddress((void**)&yw0, g_yw0);
    cudaGetSymbolAddress((void**)&x1,  g_x1);
    cudaGetSymbolAddress((void**)&y1,  g_y1);
    cudaGetSymbolAddress((void**)&xw1, g_xw1);
    cudaGetSymbolAddress((void**)&yw1, g_yw1);

    float* out = (float*)d_out;

    // K1: x@W0 tensor-core GEMM interleaved with the 4-matrix histogram
    fused_gemmx_hist_kernel<<<K2_BLOCKS, 256>>>(
        x, W0, xw0,
        hht_r, nnz_hht, h_r, nnz_h, ht_r, nnz_ht, hth_r, nnz_hth);

    // K2: fused rowptr build (scan + grid barrier + apply + cnt reset)
    scan_fused_kernel<<<SCAN_BLOCKS, 1024>>>(nnz_hht, nnz_h, nnz_ht, nnz_hth);

    // K3: y@W0 tensor-core GEMM interleaved with the COO->CSR scatter
    fused_gemmy_scatter_kernel<<<K6_BLOCKS, 256>>>(
        y, W0, yw0,
        hht_r, hht_c, hht_v, nnz_hht,
        h_r,   h_c,   h_v,   nnz_h,
        ht_r,  ht_c,  ht_v,  nnz_ht,
        hth_r, hth_c, hth_v, nnz_hth);

    // K4: layer-0 SpMM over both row spaces (fp16 gathers/out, fp32 accum)
    spmm256_dual_kernel<<<NROWS / 8 + MROWS / 8, 256>>>(xw0, yw0, x1, y1);

    // K5: layer-1 tensor-core GEMM (fp16 in, fp16 out)
    gemm1_dual_kernel<<<G1X_BLOCKS + 157, 256>>>(x1, y1, W1, xw1, yw1);

    // K6: layer-1 SpMM (fp16 gathers), writes final fp32 output
    spmm64_dual_kernel<<<NROWS / 16 + MROWS / 16, 256>>>(xw1, yw1, out);
}